// round 10
// baseline (speedup 1.0000x reference)
#include <cuda_runtime.h>
#include <stdint.h>

// ScaledNeuron: IF neuron, soft reset, V_TH=1.0, SCALE=1.0, v0=0.5.
// xs: [B=16, C=64, H=64, W=64, T=8] fp32, T contiguous.
//
// One float4 (= 4 timesteps of half a location) per lane; temporal recurrence
// stitched across the even/odd lane pair with shfl_up. MLP_p1=4 (four
// front-batched, independently lane-consecutive load streams at i + k*q).
//
// Register-lean stitch: pass 1 computes ONLY v (no spike regs); after the
// shfl, v_start = (odd lane) ? partner_v : 0.5 — for even lanes pass 2 from
// 0.5 reproduces pass 1 exactly, so pass 2 produces the final spikes for ALL
// lanes branchlessly. Spikes live 4 regs at a time (store interleaved).

__device__ __forceinline__ float if4_v(float4 x, float v) {
    // 4 IF steps, membrane potential only.
    v += x.x; v -= (v >= 1.0f) ? 1.0f : 0.0f;
    v += x.y; v -= (v >= 1.0f) ? 1.0f : 0.0f;
    v += x.z; v -= (v >= 1.0f) ? 1.0f : 0.0f;
    v += x.w; v -= (v >= 1.0f) ? 1.0f : 0.0f;
    return v;
}

__device__ __forceinline__ float4 if4_s(float4 x, float v) {
    // 4 IF steps, producing spikes.
    float s0, s1, s2, s3;
    v += x.x; s0 = (v >= 1.0f) ? 1.0f : 0.0f; v -= s0;
    v += x.y; s1 = (v >= 1.0f) ? 1.0f : 0.0f; v -= s1;
    v += x.z; s2 = (v >= 1.0f) ? 1.0f : 0.0f; v -= s2;
    v += x.w; s3 = (v >= 1.0f) ? 1.0f : 0.0f; v -= s3;
    return make_float4(s0, s1, s2, s3);
}

__global__ __launch_bounds__(256)
void scaled_neuron_kernel(const float4* __restrict__ in,
                          float4* __restrict__ out,
                          int quarter) {        // quarter = n4 / 4 (even)
    int i = blockIdx.x * blockDim.x + threadIdx.x;
    if (i >= quarter) return;

    bool odd = (threadIdx.x & 1) != 0;

    // Front-batched, all perfectly coalesced (MLP_p1 = 4).
    float4 x0 = in[i];
    float4 x1 = in[i + quarter];
    float4 x2 = in[i + 2 * quarter];
    float4 x3 = in[i + 3 * quarter];

    // Pass 1: v only (valid hand-off value on even lanes).
    float v0 = if4_v(x0, 0.5f);
    float v1 = if4_v(x1, 0.5f);
    float v2 = if4_v(x2, 0.5f);
    float v3 = if4_v(x3, 0.5f);

    // Even lane -> odd partner.
    float p0 = __shfl_up_sync(0xffffffffu, v0, 1);
    float p1 = __shfl_up_sync(0xffffffffu, v1, 1);
    float p2 = __shfl_up_sync(0xffffffffu, v2, 1);
    float p3 = __shfl_up_sync(0xffffffffu, v3, 1);

    // Pass 2 (branchless): even lanes restart from 0.5 (== pass 1),
    // odd lanes start from partner's v. Store per element to cap live regs.
    out[i]               = if4_s(x0, odd ? p0 : 0.5f);
    out[i + quarter]     = if4_s(x1, odd ? p1 : 0.5f);
    out[i + 2 * quarter] = if4_s(x2, odd ? p2 : 0.5f);
    out[i + 3 * quarter] = if4_s(x3, odd ? p3 : 0.5f);
}

extern "C" void kernel_launch(void* const* d_in, const int* in_sizes, int n_in,
                              void* d_out, int out_size) {
    const float4* in = (const float4*)d_in[0];
    float4* out = (float4*)d_out;

    int n4 = in_sizes[0] / 4;    // 8,388,608 float4
    int quarter = n4 / 4;        // 2,097,152 (even)
    int threads = 256;
    int blocks = (quarter + threads - 1) / threads;  // 8192

    scaled_neuron_kernel<<<blocks, threads>>>(in, out, quarter);
}